// round 2
// baseline (speedup 1.0000x reference)
#include <cuda_runtime.h>
#include <mma.h>
#include <cstdint>
#include <cstddef>

using namespace nvcuda;

// Problem dims
#define B_ROWS 4096
#define D_IN   1024
#define D_H    4096
#define D_OUT  1024
#define NE     8
#define EH     (NE * D_H)     // 32768
#define HALFK  (4 * D_H)      // 16384
#define NACT   5

// GEMM tiling
#define BM 128
#define BN 128
#define BK 16
#define LDAS 20    // padded A smem row stride (80B, multiple of 16B)
#define LDBS 132   // padded B smem row stride (528B, multiple of 16B)

// Scratch (device globals: allocation inside kernel_launch is forbidden)
__device__ float g_w[B_ROWS * NE];                       // gate weights
__device__ float g_hs[(size_t)B_ROWS * EH];              // 512 MB: w[b,e]*relu(x@w1+b1)
__device__ float g_oa[(size_t)B_ROWS * D_OUT];           // camp-A raw (no b2 yet)
__device__ float g_og[(size_t)B_ROWS * D_OUT];           // camp-G raw

// ---------------------------------------------------------------------------
// cp.async helpers
// ---------------------------------------------------------------------------
__device__ __forceinline__ void cp16(float* sdst, const float* gsrc) {
    uint32_t s = (uint32_t)__cvta_generic_to_shared(sdst);
    asm volatile("cp.async.cg.shared.global [%0], [%1], 16;\n" :: "r"(s), "l"(gsrc));
}
__device__ __forceinline__ void cp_commit() {
    asm volatile("cp.async.commit_group;\n");
}
__device__ __forceinline__ void cp_wait_all() {
    asm volatile("cp.async.wait_group 0;\n" ::: "memory");
}

// ---------------------------------------------------------------------------
// Kernel 1: gating. One warp per row.
// scores=(x@gw+gb)/e, softmax, top-5 (strict > => lowest index on ties, like
// jax top_k), renormalize over selected.
// ---------------------------------------------------------------------------
__global__ void gate_kernel(const float* __restrict__ x,
                            const float* __restrict__ gw,
                            const float* __restrict__ gb) {
    int warp = (blockIdx.x * blockDim.x + threadIdx.x) >> 5;
    int lane = threadIdx.x & 31;
    if (warp >= B_ROWS) return;

    const float* xr = x + (size_t)warp * D_IN;
    float acc[NE];
#pragma unroll
    for (int e = 0; e < NE; e++) acc[e] = 0.f;

    for (int i = lane; i < D_IN; i += 32) {
        float xv = xr[i];
        const float* g = gw + i * NE;
#pragma unroll
        for (int e = 0; e < NE; e++) acc[e] += xv * g[e];
    }
#pragma unroll
    for (int e = 0; e < NE; e++) {
#pragma unroll
        for (int off = 16; off > 0; off >>= 1)
            acc[e] += __shfl_xor_sync(0xffffffffu, acc[e], off);
    }

    if (lane == 0) {
        const float invT = 0.36787944117144233f;  // 1/e
        float p[NE];
        float mx = -1e30f;
#pragma unroll
        for (int e = 0; e < NE; e++) {
            p[e] = (acc[e] + gb[e]) * invT;
            mx = fmaxf(mx, p[e]);
        }
        float sum = 0.f;
#pragma unroll
        for (int e = 0; e < NE; e++) { p[e] = expf(p[e] - mx); sum += p[e]; }
        float inv = 1.f / sum;
#pragma unroll
        for (int e = 0; e < NE; e++) p[e] *= inv;

        bool sel[NE];
#pragma unroll
        for (int e = 0; e < NE; e++) sel[e] = false;
        for (int t = 0; t < NACT; t++) {
            int bi = -1; float bv = -1.f;
#pragma unroll
            for (int e = 0; e < NE; e++)
                if (!sel[e] && p[e] > bv) { bv = p[e]; bi = e; }
            sel[bi] = true;
        }
        float ws = 0.f;
#pragma unroll
        for (int e = 0; e < NE; e++) if (sel[e]) ws += p[e];
        float wi = 1.f / (ws + 1e-8f);
#pragma unroll
        for (int e = 0; e < NE; e++)
            g_w[warp * NE + e] = sel[e] ? p[e] * wi : 0.f;
    }
}

// ---------------------------------------------------------------------------
// Kernel 2: FFN layer 1 per expert.
// hs[b, e*DH + n] = w[b,e] * relu( sum_k x[b,k]*w1[e,k,n] + b1[e,n] )
// TF32 wmma, 128x128x16 tiles, cp.async double-buffered.
// grid = (D_H/BN, B/BM, NE), 256 threads (8 warps, 2x4; warp tile 64x32)
// ---------------------------------------------------------------------------
__global__ void ffn1_kernel(const float* __restrict__ x,
                            const float* __restrict__ w1,
                            const float* __restrict__ b1) {
    __shared__ __align__(16) float As[2][BM * LDAS];
    __shared__ __align__(16) float Bs[2][BK * LDBS];
    __shared__ __align__(16) float scratch[8][256];

    const int e    = blockIdx.z;
    const int row0 = blockIdx.y * BM;
    const int col0 = blockIdx.x * BN;   // within D_H
    const int tid  = threadIdx.x;

    const float* Ag = x + (size_t)row0 * D_IN;
    const float* Bg = w1 + (size_t)e * D_IN * D_H + col0;

    wmma::fragment<wmma::accumulator, 16, 16, 8, float> c[4][2];
#pragma unroll
    for (int i = 0; i < 4; i++)
#pragma unroll
        for (int j = 0; j < 2; j++) wmma::fill_fragment(c[i][j], 0.f);

    auto load_stage = [&](int st, int k0) {
        for (int f = tid; f < (BM * BK) / 4; f += 256) {       // 512 float4
            int r = f >> 2, c4 = f & 3;
            cp16(&As[st][r * LDAS + c4 * 4], Ag + (size_t)r * D_IN + k0 + c4 * 4);
        }
        for (int f = tid; f < (BK * BN) / 4; f += 256) {       // 512 float4
            int r = f >> 5, c4 = f & 31;
            cp16(&Bs[st][r * LDBS + c4 * 4], Bg + (size_t)(k0 + r) * D_H + c4 * 4);
        }
        cp_commit();
    };

    const int wid = tid >> 5;
    const int wm = wid >> 2;     // 0..1
    const int wn = wid & 3;      // 0..3

    load_stage(0, 0);
    const int KT = D_IN / BK;    // 64
    for (int kt = 0; kt < KT; kt++) {
        cp_wait_all();
        __syncthreads();
        if (kt + 1 < KT) load_stage((kt + 1) & 1, (kt + 1) * BK);
        int st = kt & 1;
#pragma unroll
        for (int kk = 0; kk < BK; kk += 8) {
            wmma::fragment<wmma::matrix_a, 16, 16, 8, wmma::precision::tf32, wmma::row_major> a[4];
            wmma::fragment<wmma::matrix_b, 16, 16, 8, wmma::precision::tf32, wmma::row_major> b[2];
#pragma unroll
            for (int i = 0; i < 4; i++) {
                wmma::load_matrix_sync(a[i], &As[st][(wm * 64 + i * 16) * LDAS + kk], LDAS);
#pragma unroll
                for (int t = 0; t < a[i].num_elements; t++)
                    a[i].x[t] = wmma::__float_to_tf32(a[i].x[t]);
            }
#pragma unroll
            for (int j = 0; j < 2; j++) {
                wmma::load_matrix_sync(b[j], &Bs[st][kk * LDBS + wn * 32 + j * 16], LDBS);
#pragma unroll
                for (int t = 0; t < b[j].num_elements; t++)
                    b[j].x[t] = wmma::__float_to_tf32(b[j].x[t]);
            }
#pragma unroll
            for (int i = 0; i < 4; i++)
#pragma unroll
                for (int j = 0; j < 2; j++)
                    wmma::mma_sync(c[i][j], a[i], b[j], c[i][j]);
        }
    }
    __syncthreads();

    // Epilogue: +b1, relu, *gate weight, store to hs
    const int lane = tid & 31;
    float* sc = scratch[wid];
    const float* b1e = b1 + (size_t)e * D_H;
#pragma unroll
    for (int i = 0; i < 4; i++) {
#pragma unroll
        for (int j = 0; j < 2; j++) {
            wmma::store_matrix_sync(sc, c[i][j], 16, wmma::mem_row_major);
            __syncwarp();
            int gr0 = row0 + wm * 64 + i * 16;
            int gc0 = col0 + wn * 32 + j * 16;
#pragma unroll
            for (int t = 0; t < 8; t++) {
                int idx = lane + 32 * t;
                int r  = gr0 + (idx >> 4);
                int cg = gc0 + (idx & 15);
                float v = sc[idx] + b1e[cg];
                v = fmaxf(v, 0.f) * g_w[r * NE + e];
                g_hs[(size_t)r * EH + (size_t)e * D_H + cg] = v;
            }
            __syncwarp();
        }
    }
}

// ---------------------------------------------------------------------------
// Kernel 3: FFN layer 2 as two large GEMMs (camps A and G via grid.z).
// oa[b,o] = sum_{k<16384} hs[b,k]      * w2flat[k,o]
// og[b,o] = sum_{k<16384} hs[b,16384+k]* w2flat[16384+k,o]
// ---------------------------------------------------------------------------
__global__ void ffn2_kernel(const float* __restrict__ w2) {
    __shared__ __align__(16) float As[2][BM * LDAS];
    __shared__ __align__(16) float Bs[2][BK * LDBS];

    const int camp = blockIdx.z;
    const int row0 = blockIdx.y * BM;
    const int col0 = blockIdx.x * BN;
    const int tid  = threadIdx.x;
    const size_t koff = (size_t)camp * HALFK;

    const float* Ag = g_hs + (size_t)row0 * EH + koff;
    const float* Bg = w2 + koff * D_OUT + col0;
    float* Cg = (camp == 0 ? g_oa : g_og) + (size_t)row0 * D_OUT + col0;

    wmma::fragment<wmma::accumulator, 16, 16, 8, float> c[4][2];
#pragma unroll
    for (int i = 0; i < 4; i++)
#pragma unroll
        for (int j = 0; j < 2; j++) wmma::fill_fragment(c[i][j], 0.f);

    auto load_stage = [&](int st, int k0) {
        for (int f = tid; f < (BM * BK) / 4; f += 256) {
            int r = f >> 2, c4 = f & 3;
            cp16(&As[st][r * LDAS + c4 * 4], Ag + (size_t)r * EH + k0 + c4 * 4);
        }
        for (int f = tid; f < (BK * BN) / 4; f += 256) {
            int r = f >> 5, c4 = f & 31;
            cp16(&Bs[st][r * LDBS + c4 * 4], Bg + (size_t)(k0 + r) * D_OUT + c4 * 4);
        }
        cp_commit();
    };

    const int wid = tid >> 5;
    const int wm = wid >> 2;
    const int wn = wid & 3;

    load_stage(0, 0);
    const int KT = HALFK / BK;   // 1024
    for (int kt = 0; kt < KT; kt++) {
        cp_wait_all();
        __syncthreads();
        if (kt + 1 < KT) load_stage((kt + 1) & 1, (kt + 1) * BK);
        int st = kt & 1;
#pragma unroll
        for (int kk = 0; kk < BK; kk += 8) {
            wmma::fragment<wmma::matrix_a, 16, 16, 8, wmma::precision::tf32, wmma::row_major> a[4];
            wmma::fragment<wmma::matrix_b, 16, 16, 8, wmma::precision::tf32, wmma::row_major> b[2];
#pragma unroll
            for (int i = 0; i < 4; i++) {
                wmma::load_matrix_sync(a[i], &As[st][(wm * 64 + i * 16) * LDAS + kk], LDAS);
#pragma unroll
                for (int t = 0; t < a[i].num_elements; t++)
                    a[i].x[t] = wmma::__float_to_tf32(a[i].x[t]);
            }
#pragma unroll
            for (int j = 0; j < 2; j++) {
                wmma::load_matrix_sync(b[j], &Bs[st][kk * LDBS + wn * 32 + j * 16], LDBS);
#pragma unroll
                for (int t = 0; t < b[j].num_elements; t++)
                    b[j].x[t] = wmma::__float_to_tf32(b[j].x[t]);
            }
#pragma unroll
            for (int i = 0; i < 4; i++)
#pragma unroll
                for (int j = 0; j < 2; j++)
                    wmma::mma_sync(c[i][j], a[i], b[j], c[i][j]);
        }
    }
    __syncthreads();

#pragma unroll
    for (int i = 0; i < 4; i++)
#pragma unroll
        for (int j = 0; j < 2; j++)
            wmma::store_matrix_sync(&Cg[(size_t)(wm * 64 + i * 16) * D_OUT + wn * 32 + j * 16],
                                    c[i][j], D_OUT, wmma::mem_row_major);
}

// ---------------------------------------------------------------------------
// Kernel 4: epilogue. Per row: add Sum_e w*b2, diff, L2 + variance, sigmoid,
// write (output, out_a, out_g) sections of d_out.
// ---------------------------------------------------------------------------
__global__ void finish_kernel(const float* __restrict__ b2,
                              const float* __restrict__ alpha,
                              const float* __restrict__ beta,
                              float* __restrict__ out) {
    __shared__ __align__(16) float sb2[NE * D_OUT];   // 32KB
    __shared__ float sw[NE];
    __shared__ float red1[8], red2[8];
    __shared__ float sph;

    const int b = blockIdx.x;
    const int tid = threadIdx.x;

    for (int i = tid; i < NE * D_OUT; i += 256) sb2[i] = b2[i];
    if (tid < NE) sw[tid] = g_w[b * NE + tid];
    __syncthreads();

    const size_t SEC = (size_t)B_ROWS * D_OUT;
    float d[4];
    float s1 = 0.f, s2 = 0.f;
#pragma unroll
    for (int t = 0; t < 4; t++) {
        int o = tid + 256 * t;
        float a = g_oa[(size_t)b * D_OUT + o];
        float g = g_og[(size_t)b * D_OUT + o];
#pragma unroll
        for (int e = 0; e < 4; e++) {
            a += sw[e]     * sb2[e * D_OUT + o];
            g += sw[4 + e] * sb2[(4 + e) * D_OUT + o];
        }
        out[SEC     + (size_t)b * D_OUT + o] = a;   // out_a
        out[2 * SEC + (size_t)b * D_OUT + o] = g;   // out_g
        float dd = a - g;
        d[t] = dd;
        s1 += dd;
        s2 += dd * dd;
    }
#pragma unroll
    for (int off = 16; off > 0; off >>= 1) {
        s1 += __shfl_xor_sync(0xffffffffu, s1, off);
        s2 += __shfl_xor_sync(0xffffffffu, s2, off);
    }
    if ((tid & 31) == 0) { red1[tid >> 5] = s1; red2[tid >> 5] = s2; }
    __syncthreads();
    if (tid == 0) {
        float t1 = 0.f, t2 = 0.f;
#pragma unroll
        for (int w = 0; w < 8; w++) { t1 += red1[w]; t2 += red2[w]; }
        float l2   = sqrtf(t2);
        float mean = t1 * (1.f / D_OUT);
        float var  = t2 * (1.f / D_OUT) - mean * mean;
        float z = alpha[0] * (l2 * (1.f + var)) + beta[0];
        sph = 2.f / (1.f + expf(-z));
    }
    __syncthreads();
    float ph = sph;
#pragma unroll
    for (int t = 0; t < 4; t++) {
        int o = tid + 256 * t;
        out[(size_t)b * D_OUT + o] = d[t] * ph;     // output
    }
}

// ---------------------------------------------------------------------------
extern "C" void kernel_launch(void* const* d_in, const int* in_sizes, int n_in,
                              void* d_out, int out_size) {
    (void)in_sizes; (void)n_in; (void)out_size;
    const float* x  = (const float*)d_in[0];
    const float* gw = (const float*)d_in[1];
    const float* gb = (const float*)d_in[2];
    const float* w1 = (const float*)d_in[3];
    const float* b1 = (const float*)d_in[4];
    const float* w2 = (const float*)d_in[5];
    const float* b2 = (const float*)d_in[6];
    const float* pa = (const float*)d_in[7];
    const float* pb = (const float*)d_in[8];
    float* out = (float*)d_out;

    gate_kernel<<<B_ROWS / 8, 256>>>(x, gw, gb);

    dim3 g1(D_H / BN, B_ROWS / BM, NE);      // (32, 32, 8)
    ffn1_kernel<<<g1, 256>>>(x, w1, b1);

    dim3 g2(D_OUT / BN, B_ROWS / BM, 2);     // (8, 32, 2)
    ffn2_kernel<<<g2, 256>>>(w2);

    finish_kernel<<<B_ROWS, 256>>>(b2, pa, pb, out);
}

// round 4
// speedup vs baseline: 5.4452x; 5.4452x over previous
#include <cuda_runtime.h>
#include <cuda_fp16.h>
#include <mma.h>
#include <cstdint>
#include <cstddef>

using namespace nvcuda;

#define B_ROWS 4096
#define D_IN   1024
#define D_H    4096
#define D_OUT  1024
#define NE     8
#define EH     32768
#define HALFK  16384
#define NACT   5

// GEMM tiling: CTA 128x128, 8 warps (2x4), warp tile 64x32, BK=32 fp16
#define BK  32
#define LDA 40     // A smem row stride in halves (80B)
#define LDB 136    // B smem row stride in halves (272B)

// Scratch (device globals; no allocation allowed)
__device__ float  g_w[B_ROWS * NE];
__device__ __half g_xh[(size_t)B_ROWS * D_IN];           // 8 MB
__device__ __half g_w1h[(size_t)NE * D_IN * D_H];        // 64 MB
__device__ __half g_w2h[(size_t)EH * D_OUT];             // 64 MB
__device__ __half g_hsh[(size_t)B_ROWS * EH];            // 256 MB
__device__ float  g_oa[(size_t)B_ROWS * D_OUT];
__device__ float  g_og[(size_t)B_ROWS * D_OUT];

// ---------------------------------------------------------------------------
__device__ __forceinline__ void cp16h(__half* sdst, const __half* gsrc) {
    uint32_t s = (uint32_t)__cvta_generic_to_shared(sdst);
    asm volatile("cp.async.cg.shared.global [%0], [%1], 16;\n" :: "r"(s), "l"(gsrc));
}
#define CP_COMMIT()   asm volatile("cp.async.commit_group;\n")
#define CP_WAIT_ALL() asm volatile("cp.async.wait_group 0;\n" ::: "memory")

// ---------------------------------------------------------------------------
// fp32 -> fp16 conversion (vectorized), dst selected by `which`
// ---------------------------------------------------------------------------
__global__ void f2h_kernel(const float4* __restrict__ src, int which, int n4) {
    int i = blockIdx.x * blockDim.x + threadIdx.x;
    if (i >= n4) return;
    float4 v = src[i];
    union { __half2 h2[2]; uint2 u; } cvt;
    cvt.h2[0] = __floats2half2_rn(v.x, v.y);
    cvt.h2[1] = __floats2half2_rn(v.z, v.w);
    uint2* dst = (which == 0) ? reinterpret_cast<uint2*>(g_xh)
               : (which == 1) ? reinterpret_cast<uint2*>(g_w1h)
                              : reinterpret_cast<uint2*>(g_w2h);
    dst[i] = cvt.u;
}

// ---------------------------------------------------------------------------
// gate (proven in R1)
// ---------------------------------------------------------------------------
__global__ void gate_kernel(const float* __restrict__ x, const float* __restrict__ gw,
                            const float* __restrict__ gb) {
    int warp = (blockIdx.x * blockDim.x + threadIdx.x) >> 5;
    int lane = threadIdx.x & 31;
    if (warp >= B_ROWS) return;
    const float* xr = x + (size_t)warp * D_IN;
    float acc[NE];
#pragma unroll
    for (int e = 0; e < NE; e++) acc[e] = 0.f;
    for (int i = lane; i < D_IN; i += 32) {
        float xv = xr[i];
        const float* g = gw + i * NE;
#pragma unroll
        for (int e = 0; e < NE; e++) acc[e] += xv * g[e];
    }
#pragma unroll
    for (int e = 0; e < NE; e++)
#pragma unroll
        for (int off = 16; off > 0; off >>= 1)
            acc[e] += __shfl_xor_sync(0xffffffffu, acc[e], off);
    if (lane == 0) {
        const float invT = 0.36787944117144233f;
        float p[NE]; float mx = -1e30f;
#pragma unroll
        for (int e = 0; e < NE; e++) { p[e] = (acc[e] + gb[e]) * invT; mx = fmaxf(mx, p[e]); }
        float sum = 0.f;
#pragma unroll
        for (int e = 0; e < NE; e++) { p[e] = expf(p[e] - mx); sum += p[e]; }
        float inv = 1.f / sum;
#pragma unroll
        for (int e = 0; e < NE; e++) p[e] *= inv;
        bool sel[NE];
#pragma unroll
        for (int e = 0; e < NE; e++) sel[e] = false;
        for (int t = 0; t < NACT; t++) {
            int bi = -1; float bv = -1.f;
#pragma unroll
            for (int e = 0; e < NE; e++)
                if (!sel[e] && p[e] > bv) { bv = p[e]; bi = e; }
            sel[bi] = true;
        }
        float ws = 0.f;
#pragma unroll
        for (int e = 0; e < NE; e++) if (sel[e]) ws += p[e];
        float wi = 1.f / (ws + 1e-8f);
#pragma unroll
        for (int e = 0; e < NE; e++) g_w[warp * NE + e] = sel[e] ? p[e] * wi : 0.f;
    }
}

// ---------------------------------------------------------------------------
// fp16 GEMM. MODE 0: FFN1 (z=expert), epilogue bias+relu+gate -> g_hsh (fp16).
//           MODE 1: FFN2 (z=camp), output fp32 to g_oa/g_og.
// ---------------------------------------------------------------------------
template <int MODE>
__global__ void __launch_bounds__(256) gemm_h(const float* __restrict__ b1) {
    __shared__ __align__(16) __half Ah[2][128 * LDA];   // 20 KB
    __shared__ __align__(16) __half Bh[2][BK * LDB];    // 17 KB
    __shared__ __align__(16) float  sc[8][256];         // 8 KB

    const int tid  = threadIdx.x;
    const int z    = blockIdx.z;
    const int row0 = blockIdx.y * 128;
    const int col0 = blockIdx.x * 128;

    const int    KT  = (MODE == 0) ? (D_IN / BK) : (HALFK / BK);
    const size_t ldA = (MODE == 0) ? D_IN : EH;
    const size_t ldB = (MODE == 0) ? D_H : D_OUT;
    const __half* Ag = (MODE == 0) ? g_xh  + (size_t)row0 * D_IN
                                   : g_hsh + (size_t)row0 * EH + (size_t)z * HALFK;
    const __half* Bg = (MODE == 0) ? g_w1h + (size_t)z * D_IN * D_H + col0
                                   : g_w2h + (size_t)z * HALFK * D_OUT + col0;

    wmma::fragment<wmma::accumulator, 16, 16, 16, float> c[4][2];
#pragma unroll
    for (int i = 0; i < 4; i++)
#pragma unroll
        for (int j = 0; j < 2; j++) wmma::fill_fragment(c[i][j], 0.f);

    auto load_stage = [&](int st, int k0) {
        for (int f = tid; f < 512; f += 256) {          // A: 128 rows x 4 segs
            int r = f >> 2, s4 = f & 3;
            cp16h(&Ah[st][r * LDA + s4 * 8], Ag + (size_t)r * ldA + k0 + s4 * 8);
        }
        for (int f = tid; f < 512; f += 256) {          // B: 32 rows x 16 segs
            int r = f >> 4, s4 = f & 15;
            cp16h(&Bh[st][r * LDB + s4 * 8], Bg + (size_t)(k0 + r) * ldB + s4 * 8);
        }
        CP_COMMIT();
    };

    const int wid = tid >> 5, lane = tid & 31;
    const int wm = wid >> 2;      // 0..1  (64-row block)
    const int wn = wid & 3;       // 0..3  (32-col block)

    load_stage(0, 0);
    for (int kt = 0; kt < KT; kt++) {
        CP_WAIT_ALL();
        __syncthreads();
        if (kt + 1 < KT) load_stage((kt + 1) & 1, (kt + 1) * BK);
        int st = kt & 1;
#pragma unroll
        for (int kk = 0; kk < BK; kk += 16) {
            wmma::fragment<wmma::matrix_a, 16, 16, 16, __half, wmma::row_major> a[4];
            wmma::fragment<wmma::matrix_b, 16, 16, 16, __half, wmma::row_major> b[2];
#pragma unroll
            for (int i = 0; i < 4; i++)
                wmma::load_matrix_sync(a[i], &Ah[st][(wm * 64 + i * 16) * LDA + kk], LDA);
#pragma unroll
            for (int j = 0; j < 2; j++)
                wmma::load_matrix_sync(b[j], &Bh[st][kk * LDB + wn * 32 + j * 16], LDB);
#pragma unroll
            for (int i = 0; i < 4; i++)
#pragma unroll
                for (int j = 0; j < 2; j++)
                    wmma::mma_sync(c[i][j], a[i], b[j], c[i][j]);
        }
    }
    __syncthreads();

    if (MODE == 0) {
        const float* b1e = b1 + (size_t)z * D_H;
#pragma unroll
        for (int i = 0; i < 4; i++) {
#pragma unroll
            for (int j = 0; j < 2; j++) {
                wmma::store_matrix_sync(sc[wid], c[i][j], 16, wmma::mem_row_major);
                __syncwarp();
                int gr0 = row0 + wm * 64 + i * 16;
                int gc0 = col0 + wn * 32 + j * 16;
#pragma unroll
                for (int t = 0; t < 8; t++) {
                    int idx = lane + 32 * t;
                    int r  = gr0 + (idx >> 4);
                    int cc = gc0 + (idx & 15);
                    float v = sc[wid][idx] + b1e[cc];
                    v = fmaxf(v, 0.f) * g_w[r * NE + z];
                    g_hsh[(size_t)r * EH + (size_t)z * D_H + cc] = __float2half_rn(v);
                }
                __syncwarp();
            }
        }
    } else {
        float* Cg = (z == 0 ? g_oa : g_og) + (size_t)row0 * D_OUT + col0;
#pragma unroll
        for (int i = 0; i < 4; i++)
#pragma unroll
            for (int j = 0; j < 2; j++)
                wmma::store_matrix_sync(&Cg[(size_t)(wm * 64 + i * 16) * D_OUT + wn * 32 + j * 16],
                                        c[i][j], D_OUT, wmma::mem_row_major);
    }
}

// ---------------------------------------------------------------------------
// finish (proven in R1)
// ---------------------------------------------------------------------------
__global__ void finish_kernel(const float* __restrict__ b2, const float* __restrict__ alpha,
                              const float* __restrict__ beta, float* __restrict__ out) {
    __shared__ __align__(16) float sb2[NE * D_OUT];
    __shared__ float sw[NE];
    __shared__ float red1[8], red2[8];
    __shared__ float sph;
    const int b = blockIdx.x, tid = threadIdx.x;
    for (int i = tid; i < NE * D_OUT; i += 256) sb2[i] = b2[i];
    if (tid < NE) sw[tid] = g_w[b * NE + tid];
    __syncthreads();
    const size_t SEC = (size_t)B_ROWS * D_OUT;
    float d[4]; float s1 = 0.f, s2 = 0.f;
#pragma unroll
    for (int t = 0; t < 4; t++) {
        int o = tid + 256 * t;
        float a = g_oa[(size_t)b * D_OUT + o];
        float g = g_og[(size_t)b * D_OUT + o];
#pragma unroll
        for (int e = 0; e < 4; e++) {
            a += sw[e] * sb2[e * D_OUT + o];
            g += sw[4 + e] * sb2[(4 + e) * D_OUT + o];
        }
        out[SEC + (size_t)b * D_OUT + o] = a;
        out[2 * SEC + (size_t)b * D_OUT + o] = g;
        float dd = a - g; d[t] = dd; s1 += dd; s2 += dd * dd;
    }
#pragma unroll
    for (int off = 16; off > 0; off >>= 1) {
        s1 += __shfl_xor_sync(0xffffffffu, s1, off);
        s2 += __shfl_xor_sync(0xffffffffu, s2, off);
    }
    if ((tid & 31) == 0) { red1[tid >> 5] = s1; red2[tid >> 5] = s2; }
    __syncthreads();
    if (tid == 0) {
        float t1 = 0.f, t2 = 0.f;
#pragma unroll
        for (int w = 0; w < 8; w++) { t1 += red1[w]; t2 += red2[w]; }
        float l2 = sqrtf(t2);
        float mean = t1 * (1.f / D_OUT);
        float var = t2 * (1.f / D_OUT) - mean * mean;
        float zz = alpha[0] * (l2 * (1.f + var)) + beta[0];
        sph = 2.f / (1.f + expf(-zz));
    }
    __syncthreads();
    float ph = sph;
#pragma unroll
    for (int t = 0; t < 4; t++) {
        int o = tid + 256 * t;
        out[(size_t)b * D_OUT + o] = d[t] * ph;
    }
}

// ---------------------------------------------------------------------------
extern "C" void kernel_launch(void* const* d_in, const int* in_sizes, int n_in,
                              void* d_out, int out_size) {
    (void)in_sizes; (void)n_in; (void)out_size;
    const float* x  = (const float*)d_in[0];
    const float* gw = (const float*)d_in[1];
    const float* gb = (const float*)d_in[2];
    const float* w1 = (const float*)d_in[3];
    const float* b1 = (const float*)d_in[4];
    const float* w2 = (const float*)d_in[5];
    const float* b2 = (const float*)d_in[6];
    const float* pa = (const float*)d_in[7];
    const float* pb = (const float*)d_in[8];
    float* out = (float*)d_out;

    gate_kernel<<<B_ROWS / 8, 256>>>(x, gw, gb);

    int n4x = (B_ROWS * D_IN) / 4;                 // 1,048,576
    int n4w = (NE * D_IN * D_H) / 4;               // 8,388,608
    f2h_kernel<<<n4x / 256, 256>>>((const float4*)x, 0, n4x);
    f2h_kernel<<<n4w / 256, 256>>>((const float4*)w1, 1, n4w);
    f2h_kernel<<<n4w / 256, 256>>>((const float4*)w2, 2, n4w);

    gemm_h<0><<<dim3(D_H / 128, B_ROWS / 128, NE), 256>>>(b1);       // (32,32,8)
    gemm_h<1><<<dim3(D_OUT / 128, B_ROWS / 128, 2), 256>>>(nullptr); // (8,32,2)

    finish_kernel<<<B_ROWS, 256>>>(b2, pa, pb, out);
}